// round 8
// baseline (speedup 1.0000x reference)
#include <cuda_runtime.h>

#define NROI 1024
#define NB   8
#define FH   160
#define FW   160
#define CC   256
#define CROPN 14
#define PO   7

// Precomputed per-(roi, sample) geometry: {w, lo_idx(bits), hi_idx(bits), valid}
__device__ float4 g_yd[NROI * CROPN];
__device__ float4 g_xd[NROI * CROPN];
__device__ int    g_perm[NROI];          // sorted: (roi << 4) | batch

// Fused setup: per-ROI sample-descriptor precompute + bucket sort by image id.
__global__ __launch_bounds__(NROI) void roi_setup_kernel(
    const float* __restrict__ rois,
    const float* __restrict__ iminfo)
{
    __shared__ int cnt[NB];
    __shared__ int off[NB];
    const int i = threadIdx.x;               // 0..1023, one ROI each

    const float rid = rois[i * 5 + 0];
    const float rx1 = rois[i * 5 + 1];
    const float ry1 = rois[i * 5 + 2];
    const float rx2 = rois[i * 5 + 3];
    const float ry2 = rois[i * 5 + 4];
    const float imh = iminfo[i * 2 + 0];
    const float imw = iminfo[i * 2 + 1];

    const float ybase = (ry1 / imh) * (float)(FH - 1);
    const float xbase = (rx1 / imw) * (float)(FW - 1);
    const float ystep = ((ry2 - ry1) / imh) * (float)(FH - 1) / (float)(CROPN - 1);
    const float xstep = ((rx2 - rx1) / imw) * (float)(FW - 1) / (float)(CROPN - 1);

    #pragma unroll
    for (int s = 0; s < CROPN; ++s) {
        // y axis
        {
            const float y  = fmaf((float)s, ystep, ybase);
            const float vy = (y >= 0.0f && y <= (float)(FH - 1)) ? 1.0f : 0.0f;
            const float yf = floorf(y);
            const int   yl = (int)fminf(fmaxf(yf,        0.0f), (float)(FH - 1));
            const int   yh = (int)fminf(fmaxf(yf + 1.0f, 0.0f), (float)(FH - 1));
            g_yd[i * CROPN + s] = make_float4(y - yf,
                                              __int_as_float(yl * (FW * CC / 2)),
                                              __int_as_float(yh * (FW * CC / 2)),
                                              vy);
        }
        // x axis
        {
            const float x  = fmaf((float)s, xstep, xbase);
            const float vx = (x >= 0.0f && x <= (float)(FW - 1)) ? 1.0f : 0.0f;
            const float xf = floorf(x);
            const int   xl = (int)fminf(fmaxf(xf,        0.0f), (float)(FW - 1));
            const int   xh = (int)fminf(fmaxf(xf + 1.0f, 0.0f), (float)(FW - 1));
            g_xd[i * CROPN + s] = make_float4(x - xf,
                                              __int_as_float(xl * (CC / 2)),
                                              __int_as_float(xh * (CC / 2)),
                                              vx);
        }
    }

    // bucket sort by image id -> g_perm (concurrent waves share one image in L2)
    if (i < NB) cnt[i] = 0;
    __syncthreads();
    const int b = (int)rid;
    atomicAdd(&cnt[b], 1);
    __syncthreads();
    if (i == 0) {
        int s = 0;
        for (int k = 0; k < NB; ++k) { off[k] = s; s += cnt[k]; }
    }
    __syncthreads();
    const int pos = atomicAdd(&off[b], 1);
    g_perm[pos] = (i << 4) | b;
}

// One block per (sorted-roi, pooled-row). 448 threads = 7 px * 64 lanes.
// Lane t owns channels {2t, 2t+1, 128+2t, 128+2t+1} via LDG.64 pairs.
// All sample geometry comes from broadcast descriptor loads.
__global__ __launch_bounds__(448, 4) void roi_pool_kernel(
    const float* __restrict__ img,
    float* __restrict__ out)
{
    const int blk = blockIdx.x;
    const int sr  = blk / PO;
    const int py  = blk - sr * PO;
    const int pk  = g_perm[sr];
    const int roi = pk >> 4;
    const int b   = pk & 15;
    const int px  = threadIdx.x >> 6;        // 0..6
    const int t   = threadIdx.x & 63;        // lane within channel dim

    const float2* imgb = (const float2*)(img + (size_t)b * (FH * FW * CC)) + t;

    float best0 = -3.402823466e38f;
    float best1 = -3.402823466e38f;
    float best2 = -3.402823466e38f;
    float best3 = -3.402823466e38f;

    #pragma unroll
    for (int dyi = 0; dyi < 2; ++dyi) {
        const float4 yd = __ldg(&g_yd[roi * CROPN + 2 * py + dyi]);
        const float  wy = yd.x;
        const float  vy = yd.w;
        const float2* rowl = imgb + __float_as_int(yd.y);
        const float2* rowh = imgb + __float_as_int(yd.z);

        #pragma unroll
        for (int dxi = 0; dxi < 2; ++dxi) {
            const float4 xd = __ldg(&g_xd[roi * CROPN + 2 * px + dxi]);
            const float  wx = xd.x;
            const float  vv = vy * xd.w;
            const int    xl = __float_as_int(xd.y);
            const int    xh = __float_as_int(xd.z);

            const float2* atl = rowl + xl;
            const float2* atr = rowl + xh;
            const float2* abl = rowh + xl;
            const float2* abr = rowh + xh;

            const float2 tlA = __ldg(atl), tlB = __ldg(atl + 64);
            const float2 trA = __ldg(atr), trB = __ldg(atr + 64);
            const float2 blA = __ldg(abl), blB = __ldg(abl + 64);
            const float2 brA = __ldg(abr), brB = __ldg(abr + 64);

            float top, bot, v;

            top = fmaf(trA.x - tlA.x, wx, tlA.x);
            bot = fmaf(brA.x - blA.x, wx, blA.x);
            v   = fmaf(bot - top, wy, top) * vv;
            best0 = fmaxf(best0, v);

            top = fmaf(trA.y - tlA.y, wx, tlA.y);
            bot = fmaf(brA.y - blA.y, wx, blA.y);
            v   = fmaf(bot - top, wy, top) * vv;
            best1 = fmaxf(best1, v);

            top = fmaf(trB.x - tlB.x, wx, tlB.x);
            bot = fmaf(brB.x - blB.x, wx, blB.x);
            v   = fmaf(bot - top, wy, top) * vv;
            best2 = fmaxf(best2, v);

            top = fmaf(trB.y - tlB.y, wx, tlB.y);
            bot = fmaf(brB.y - blB.y, wx, blB.y);
            v   = fmaf(bot - top, wy, top) * vv;
            best3 = fmaxf(best3, v);
        }
    }

    float2* o = (float2*)(out + ((size_t)(roi * PO + py) * PO + px) * CC) + t;
    float2 s0; s0.x = best0; s0.y = best1;
    float2 s1; s1.x = best2; s1.y = best3;
    __stcs(o,      s0);
    __stcs(o + 64, s1);
}

extern "C" void kernel_launch(void* const* d_in, const int* in_sizes, int n_in,
                              void* d_out, int out_size)
{
    (void)in_sizes; (void)n_in; (void)out_size;
    const float* img    = (const float*)d_in[0];
    const float* rois   = (const float*)d_in[1];
    const float* iminfo = (const float*)d_in[2];
    float*       out    = (float*)d_out;

    roi_setup_kernel<<<1, NROI>>>(rois, iminfo);
    roi_pool_kernel<<<NROI * PO, 448>>>(img, out);
}

// round 10
// speedup vs baseline: 1.2422x; 1.2422x over previous
#include <cuda_runtime.h>

#define NROI 1024
#define NB   8
#define FH   160
#define FW   160
#define CC   256
#define CROPN 14
#define PO   7

// Per-ROI params: {ybase, ystep, xbase, xstep}; batch packed into g_perm.
__device__ float4 g_rp[NROI];
__device__ int    g_perm[NROI];          // (roi << 4) | batch

// Light fused setup: per-ROI params + bucket sort by image id (one block).
__global__ __launch_bounds__(NROI) void roi_setup_kernel(
    const float* __restrict__ rois,
    const float* __restrict__ iminfo)
{
    __shared__ int cnt[NB];
    __shared__ int off[NB];
    const int i = threadIdx.x;               // one ROI per thread

    const float rid = rois[i * 5 + 0];
    const float rx1 = rois[i * 5 + 1];
    const float ry1 = rois[i * 5 + 2];
    const float rx2 = rois[i * 5 + 3];
    const float ry2 = rois[i * 5 + 4];
    const float imh = iminfo[i * 2 + 0];
    const float imw = iminfo[i * 2 + 1];

    const float ybase = (ry1 / imh) * (float)(FH - 1);
    const float xbase = (rx1 / imw) * (float)(FW - 1);
    const float ystep = ((ry2 - ry1) / imh) * (float)(FH - 1) / (float)(CROPN - 1);
    const float xstep = ((rx2 - rx1) / imw) * (float)(FW - 1) / (float)(CROPN - 1);

    g_rp[i] = make_float4(ybase, ystep, xbase, xstep);

    if (i < NB) cnt[i] = 0;
    __syncthreads();
    const int b = (int)rid;
    atomicAdd(&cnt[b], 1);
    __syncthreads();
    if (i == 0) {
        int s = 0;
        for (int k = 0; k < NB; ++k) { off[k] = s; s += cnt[k]; }
    }
    __syncthreads();
    const int pos = atomicAdd(&off[b], 1);
    g_perm[pos] = (i << 4) | b;
}

// One channel-half window evaluation with CS distinct x-columns.
// CS==2: both samples share cols {xo0,xo1}. CS==3: cols {xo0,xo1,xo3},
// sample1 = (xo1,xo3). CS==4: sample0=(xo0,xo1), sample1=(xo2,xo3).
template <int CS>
__device__ __forceinline__ void do_half(
    const float2* __restrict__ rl, const float2* __restrict__ rh,
    int xo0, int xo1, int xo2, int xo3,
    float wx0, float wx1, float wy, float vv0, float vv1,
    float& b0, float& b1)
{
    float s0tx, s0ty, s0bx, s0by, s1tx, s1ty, s1bx, s1by;

    if (CS == 2) {
        const float2 t0 = __ldg(rl + xo0), t1 = __ldg(rl + xo1);
        const float2 c0 = __ldg(rh + xo0), c1 = __ldg(rh + xo1);
        s0tx = fmaf(t1.x - t0.x, wx0, t0.x);  s0ty = fmaf(t1.y - t0.y, wx0, t0.y);
        s0bx = fmaf(c1.x - c0.x, wx0, c0.x);  s0by = fmaf(c1.y - c0.y, wx0, c0.y);
        s1tx = fmaf(t1.x - t0.x, wx1, t0.x);  s1ty = fmaf(t1.y - t0.y, wx1, t0.y);
        s1bx = fmaf(c1.x - c0.x, wx1, c0.x);  s1by = fmaf(c1.y - c0.y, wx1, c0.y);
    } else if (CS == 3) {
        const float2 t0 = __ldg(rl + xo0), t1 = __ldg(rl + xo1), t2 = __ldg(rl + xo3);
        const float2 c0 = __ldg(rh + xo0), c1 = __ldg(rh + xo1), c2 = __ldg(rh + xo3);
        s0tx = fmaf(t1.x - t0.x, wx0, t0.x);  s0ty = fmaf(t1.y - t0.y, wx0, t0.y);
        s0bx = fmaf(c1.x - c0.x, wx0, c0.x);  s0by = fmaf(c1.y - c0.y, wx0, c0.y);
        s1tx = fmaf(t2.x - t1.x, wx1, t1.x);  s1ty = fmaf(t2.y - t1.y, wx1, t1.y);
        s1bx = fmaf(c2.x - c1.x, wx1, c1.x);  s1by = fmaf(c2.y - c1.y, wx1, c1.y);
    } else {
        const float2 t0 = __ldg(rl + xo0), t1 = __ldg(rl + xo1);
        const float2 t2 = __ldg(rl + xo2), t3 = __ldg(rl + xo3);
        const float2 c0 = __ldg(rh + xo0), c1 = __ldg(rh + xo1);
        const float2 c2 = __ldg(rh + xo2), c3 = __ldg(rh + xo3);
        s0tx = fmaf(t1.x - t0.x, wx0, t0.x);  s0ty = fmaf(t1.y - t0.y, wx0, t0.y);
        s0bx = fmaf(c1.x - c0.x, wx0, c0.x);  s0by = fmaf(c1.y - c0.y, wx0, c0.y);
        s1tx = fmaf(t3.x - t2.x, wx1, t2.x);  s1ty = fmaf(t3.y - t2.y, wx1, t2.y);
        s1bx = fmaf(c3.x - c2.x, wx1, c2.x);  s1by = fmaf(c3.y - c2.y, wx1, c2.y);
    }

    float v;
    v = fmaf(s0bx - s0tx, wy, s0tx) * vv0;  b0 = fmaxf(b0, v);
    v = fmaf(s1bx - s1tx, wy, s1tx) * vv1;  b0 = fmaxf(b0, v);
    v = fmaf(s0by - s0ty, wy, s0ty) * vv0;  b1 = fmaxf(b1, v);
    v = fmaf(s1by - s1ty, wy, s1ty) * vv1;  b1 = fmaxf(b1, v);
}

template <int CS>
__device__ __forceinline__ void run_window(
    const float2* __restrict__ imgb, int py,
    float ybase, float ystep,
    int xo0, int xo1, int xo2, int xo3,
    float wx0, float wx1, float vx0, float vx1,
    float& best0, float& best1, float& best2, float& best3)
{
    #pragma unroll
    for (int dyi = 0; dyi < 2; ++dyi) {
        const int   iy = 2 * py + dyi;
        const float y  = fmaf((float)iy, ystep, ybase);
        const float vy = (y >= 0.0f && y <= (float)(FH - 1)) ? 1.0f : 0.0f;
        const float yf = floorf(y);
        const float wy = y - yf;
        const int   yli = (int)fminf(fmaxf(yf,        0.0f), (float)(FH - 1));
        const int   yhi = (int)fminf(fmaxf(yf + 1.0f, 0.0f), (float)(FH - 1));

        const float2* rowl = imgb + yli * (FW * CC / 2);
        const float2* rowh = imgb + yhi * (FW * CC / 2);

        const float vv0 = vy * vx0;
        const float vv1 = vy * vx1;

        do_half<CS>(rowl,      rowh,      xo0, xo1, xo2, xo3,
                    wx0, wx1, wy, vv0, vv1, best0, best1);
        do_half<CS>(rowl + 64, rowh + 64, xo0, xo1, xo2, xo3,
                    wx0, wx1, wy, vv0, vv1, best2, best3);
    }
}

// One block per (sorted-roi, pooled-row). 448 threads = 7 px * 64 lanes.
// Lane t owns channels {2t,2t+1,128+2t,128+2t+1} via LDG.64.
// X-tap dedup: when the window's two samples share columns (warp-uniform),
// load 2 or 3 columns instead of 4.
__global__ __launch_bounds__(448, 4) void roi_pool_kernel(
    const float* __restrict__ img,
    float* __restrict__ out)
{
    const int blk = blockIdx.x;
    const int sr  = blk / PO;
    const int py  = blk - sr * PO;
    const int pk  = g_perm[sr];
    const int roi = pk >> 4;
    const int b   = pk & 15;
    const int px  = threadIdx.x >> 6;        // 0..6, warp-uniform
    const int t   = threadIdx.x & 63;

    const float4 rp = __ldg(&g_rp[roi]);
    const float ybase = rp.x, ystep = rp.y, xbase = rp.z, xstep = rp.w;

    const float2* imgb = (const float2*)(img + (size_t)b * (FH * FW * CC)) + t;

    // X geometry for both window samples (warp-uniform)
    const float x0  = fmaf((float)(2 * px),     xstep, xbase);
    const float x1  = fmaf((float)(2 * px + 1), xstep, xbase);
    const float vx0 = (x0 >= 0.0f && x0 <= (float)(FW - 1)) ? 1.0f : 0.0f;
    const float vx1 = (x1 >= 0.0f && x1 <= (float)(FW - 1)) ? 1.0f : 0.0f;
    const float xf0 = floorf(x0), xf1 = floorf(x1);
    const float wx0 = x0 - xf0,   wx1 = x1 - xf1;
    const int xl0 = (int)fminf(fmaxf(xf0,        0.0f), (float)(FW - 1));
    const int xh0 = (int)fminf(fmaxf(xf0 + 1.0f, 0.0f), (float)(FW - 1));
    const int xl1 = (int)fminf(fmaxf(xf1,        0.0f), (float)(FW - 1));
    const int xh1 = (int)fminf(fmaxf(xf1 + 1.0f, 0.0f), (float)(FW - 1));

    const int xo0 = xl0 * (CC / 2);
    const int xo1 = xh0 * (CC / 2);
    const int xo2 = xl1 * (CC / 2);
    const int xo3 = xh1 * (CC / 2);

    float best0 = -3.402823466e38f;
    float best1 = -3.402823466e38f;
    float best2 = -3.402823466e38f;
    float best3 = -3.402823466e38f;

    // Warp-uniform case select, hoisted outside the loop (one branch region)
    if (xl1 == xl0) {
        run_window<2>(imgb, py, ybase, ystep, xo0, xo1, xo2, xo3,
                      wx0, wx1, vx0, vx1, best0, best1, best2, best3);
    } else if (xl1 == xh0) {
        run_window<3>(imgb, py, ybase, ystep, xo0, xo1, xo2, xo3,
                      wx0, wx1, vx0, vx1, best0, best1, best2, best3);
    } else {
        run_window<4>(imgb, py, ybase, ystep, xo0, xo1, xo2, xo3,
                      wx0, wx1, vx0, vx1, best0, best1, best2, best3);
    }

    float2* o = (float2*)(out + ((size_t)(roi * PO + py) * PO + px) * CC) + t;
    float2 s0; s0.x = best0; s0.y = best1;
    float2 s1; s1.x = best2; s1.y = best3;
    __stcs(o,      s0);
    __stcs(o + 64, s1);
}

extern "C" void kernel_launch(void* const* d_in, const int* in_sizes, int n_in,
                              void* d_out, int out_size)
{
    (void)in_sizes; (void)n_in; (void)out_size;
    const float* img    = (const float*)d_in[0];
    const float* rois   = (const float*)d_in[1];
    const float* iminfo = (const float*)d_in[2];
    float*       out    = (float*)d_out;

    roi_setup_kernel<<<1, NROI>>>(rois, iminfo);
    roi_pool_kernel<<<NROI * PO, 448>>>(img, out);
}